// round 2
// baseline (speedup 1.0000x reference)
#include <cuda_runtime.h>
#include <math.h>

#define B_   8
#define T_   512
#define DM_  1024
#define H_   16
#define DH_  64
#define P_   3584
#define BT_  (B_*T_)     // 4096

// ---------------- scratch (device globals; zero-initialized at load) ----------------
__device__ float g_qraw[BT_*DM_];
__device__ float g_kraw[BT_*DM_];
__device__ float g_vraw[BT_*DM_];
__device__ float g_q  [B_*H_*T_*DH_];
__device__ float g_kn [B_*H_*T_*DH_];
__device__ float g_vn [B_*H_*T_*DH_];
__device__ float g_attn[BT_*DM_];

// ---------------- QKV projection GEMM: C = A*W + bias  (128x128x8 tiles) ----------------
__global__ __launch_bounds__(256) void gemm_qkv_kernel(
    const float* __restrict__ A,
    const float* __restrict__ Wq, const float* __restrict__ bq,
    const float* __restrict__ Wk, const float* __restrict__ bk,
    const float* __restrict__ Wv, const float* __restrict__ bv,
    const int*   __restrict__ nc)
{
    const float* Wm; const float* bias; float* C;
    int z = blockIdx.z;
    if (z == 0)      { Wm = Wq; bias = bq; C = g_qraw; }
    else if (z == 1) { Wm = Wk; bias = bk; C = g_kraw; }
    else             { Wm = Wv; bias = bv; C = g_vraw; }

    int row0 = blockIdx.y * 128;
    int b    = row0 / T_;
    if ((row0 % T_) >= nc[b]) return;   // fully-masked row block: downstream writes zeros
    int col0 = blockIdx.x * 128;

    __shared__ float As[8][128];
    __shared__ float Bs[8][128];

    int tid  = threadIdx.x;
    int tx   = tid & 15;
    int ty   = tid >> 4;
    int aRow = tid >> 1;
    int aCol = (tid & 1) << 2;
    int bRow = tid >> 5;
    int bCol = (tid & 31) << 2;

    const float* Aptr = A  + (size_t)(row0 + aRow) * DM_ + aCol;
    const float* Bptr = Wm + (size_t)bRow * DM_ + col0 + bCol;

    float acc[8][8];
#pragma unroll
    for (int i = 0; i < 8; i++)
#pragma unroll
        for (int j = 0; j < 8; j++) acc[i][j] = 0.f;

    for (int k0 = 0; k0 < DM_; k0 += 8) {
        float4 av = *(const float4*)(Aptr + k0);
        float4 bv4 = *(const float4*)(Bptr + (size_t)k0 * DM_);
        __syncthreads();
        As[aCol+0][aRow] = av.x;
        As[aCol+1][aRow] = av.y;
        As[aCol+2][aRow] = av.z;
        As[aCol+3][aRow] = av.w;
        *(float4*)&Bs[bRow][bCol] = bv4;
        __syncthreads();
#pragma unroll
        for (int kk = 0; kk < 8; kk++) {
            float ar[8], br[8];
            *(float4*)(&ar[0]) = *(const float4*)(&As[kk][ty*8]);
            *(float4*)(&ar[4]) = *(const float4*)(&As[kk][ty*8+4]);
            *(float4*)(&br[0]) = *(const float4*)(&Bs[kk][tx*8]);
            *(float4*)(&br[4]) = *(const float4*)(&Bs[kk][tx*8+4]);
#pragma unroll
            for (int i = 0; i < 8; i++)
#pragma unroll
                for (int j = 0; j < 8; j++)
                    acc[i][j] = fmaf(ar[i], br[j], acc[i][j]);
        }
    }

#pragma unroll
    for (int i = 0; i < 8; i++) {
        float* crow = C + (size_t)(row0 + ty*8 + i) * DM_ + col0 + tx*8;
#pragma unroll
        for (int j = 0; j < 8; j += 4) {
            float4 o;
            o.x = acc[i][j+0] + bias[col0 + tx*8 + j+0];
            o.y = acc[i][j+1] + bias[col0 + tx*8 + j+1];
            o.z = acc[i][j+2] + bias[col0 + tx*8 + j+2];
            o.w = acc[i][j+3] + bias[col0 + tx*8 + j+3];
            *(float4*)(crow + j) = o;
        }
    }
}

// ---------------- RoPE + validity mask + transpose to [B,H,T,DH] ----------------
__global__ __launch_bounds__(256) void rope_kernel(
    const float* __restrict__ rcos, const float* __restrict__ rsin,
    const int* __restrict__ nc)
{
    int idx = blockIdx.x * 256 + threadIdx.x;
    if (idx >= BT_*DM_) return;
    int bt = idx >> 10;       // / DM_
    int ch = idx & 1023;
    int b  = bt >> 9;         // / T_
    int t  = bt & 511;
    int h  = ch >> 6;
    int d  = ch & 63;

    bool valid = (t < nc[b]);
    float c = rcos[(t << 6) + d];
    float s = rsin[(t << 6) + d];
    int pair = (d < 32) ? (idx + 32) : (idx - 32);

    float q  = g_qraw[idx];
    float k  = g_kraw[idx];
    float v  = g_vraw[idx];
    float qp = g_qraw[pair];
    float kp = g_kraw[pair];
    float qr = (d < 32) ? -qp : qp;
    float kr = (d < 32) ? -kp : kp;

    size_t off = (((size_t)b * H_ + h) * T_ + t) * DH_ + d;
    g_q [off] = valid ? (q*c + qr*s) * 0.125f : 0.f;   // fold score scale 1/sqrt(64)
    g_kn[off] = valid ? (k*c + kr*s) : 0.f;
    g_vn[off] = valid ? v : 0.f;
}

// ---------------- Flash attention: CTA = (64 q-rows, h, b), key blocks of 32 ----------------
__global__ __launch_bounds__(128) void attn_kernel(
    const float* __restrict__ past_k, const float* __restrict__ past_v,
    const int* __restrict__ plen, const int* __restrict__ nc)
{
    __shared__ float Qs[64][65];    // stride 65: conflict-free scalar reads
    __shared__ float KPs[2112];     // K tile (stride 65, 32x64) reused as P tile (stride 33, 64x32)
    __shared__ float Vs[32][68];    // stride 68: float4-aligned reads

    int b  = blockIdx.z;
    int h  = blockIdx.y;
    int t0 = blockIdx.x * 64;
    int Nn = nc[b];
    if (t0 >= Nn) return;           // whole q tile masked downstream
    int Tp = plen[b];
    if (Tp < 0) Tp = 0; if (Tp > P_) Tp = P_;
    int Ltot = Tp + Nn;             // softmax extent (includes zero-keys in [Tp, min(P,Ltot)))

    int tid = threadIdx.x;
    int tx  = tid & 7;              // key-col group (4 cols) / dh group (8 cols)
    int ty  = tid >> 3;             // q-row group (4 rows), 0..15

    size_t bh = (size_t)b * H_ + h;
    const float* qbase = g_q  + (bh * T_ + t0) * DH_;
    const float* knb   = g_kn + bh * T_ * DH_;
    const float* vnb   = g_vn + bh * T_ * DH_;
    const float* pkb   = past_k + bh * P_ * DH_;
    const float* pvb   = past_v + bh * P_ * DH_;

    // load Q tile (scaled q already)
    for (int i = tid; i < 64*16; i += 128) {
        int r = i >> 4, c4 = (i & 15) << 2;
        float4 v = *(const float4*)(qbase + r*DH_ + c4);
        Qs[r][c4+0] = v.x; Qs[r][c4+1] = v.y; Qs[r][c4+2] = v.z; Qs[r][c4+3] = v.w;
    }

    float m[4], l[4], O[4][8];
#pragma unroll
    for (int r = 0; r < 4; r++) {
        m[r] = -1e30f; l[r] = 0.f;
#pragma unroll
        for (int c = 0; c < 8; c++) O[r][c] = 0.f;
    }
    __syncthreads();

    for (int j0 = 0; j0 < Ltot; j0 += 32) {
        // load K,V block (source select: past / zero / new)
        for (int i = tid; i < 32*16; i += 128) {
            int r = i >> 4, c4 = (i & 15) << 2;
            int key = j0 + r;
            float4 kv = make_float4(0.f,0.f,0.f,0.f);
            float4 vv = make_float4(0.f,0.f,0.f,0.f);
            if (key < Tp) {
                kv = *(const float4*)(pkb + (size_t)key*DH_ + c4);
                vv = *(const float4*)(pvb + (size_t)key*DH_ + c4);
            } else if (key >= P_ && key < Ltot) {
                kv = *(const float4*)(knb + (size_t)(key - P_)*DH_ + c4);
                vv = *(const float4*)(vnb + (size_t)(key - P_)*DH_ + c4);
            }
            KPs[r*65 + c4+0] = kv.x; KPs[r*65 + c4+1] = kv.y;
            KPs[r*65 + c4+2] = kv.z; KPs[r*65 + c4+3] = kv.w;
            *(float4*)&Vs[r][c4] = vv;
        }
        __syncthreads();

        // S = Q K^T frag: rows ty*4..+3, cols tx*4..+3
        float S[4][4];
#pragma unroll
        for (int r = 0; r < 4; r++)
#pragma unroll
            for (int c = 0; c < 4; c++) S[r][c] = 0.f;
#pragma unroll 4
        for (int d = 0; d < 64; d++) {
            float q0 = Qs[ty*4+0][d], q1 = Qs[ty*4+1][d];
            float q2 = Qs[ty*4+2][d], q3 = Qs[ty*4+3][d];
            float k0 = KPs[(tx*4+0)*65 + d], k1 = KPs[(tx*4+1)*65 + d];
            float k2 = KPs[(tx*4+2)*65 + d], k3 = KPs[(tx*4+3)*65 + d];
            S[0][0]=fmaf(q0,k0,S[0][0]); S[0][1]=fmaf(q0,k1,S[0][1]); S[0][2]=fmaf(q0,k2,S[0][2]); S[0][3]=fmaf(q0,k3,S[0][3]);
            S[1][0]=fmaf(q1,k0,S[1][0]); S[1][1]=fmaf(q1,k1,S[1][1]); S[1][2]=fmaf(q1,k2,S[1][2]); S[1][3]=fmaf(q1,k3,S[1][3]);
            S[2][0]=fmaf(q2,k0,S[2][0]); S[2][1]=fmaf(q2,k1,S[2][1]); S[2][2]=fmaf(q2,k2,S[2][2]); S[2][3]=fmaf(q2,k3,S[2][3]);
            S[3][0]=fmaf(q3,k0,S[3][0]); S[3][1]=fmaf(q3,k1,S[3][1]); S[3][2]=fmaf(q3,k2,S[3][2]); S[3][3]=fmaf(q3,k3,S[3][3]);
        }
        // exclude keys >= Ltot (ref: -1e9 mask). zero-keys in [Tp,P) stay at score 0 (included).
#pragma unroll
        for (int c = 0; c < 4; c++) {
            if (j0 + tx*4 + c >= Ltot) {
#pragma unroll
                for (int r = 0; r < 4; r++) S[r][c] = -1e9f;
            }
        }
        // online softmax update (row reduce across 8 tx lanes)
        float p[4][4];
#pragma unroll
        for (int r = 0; r < 4; r++) {
            float bm = fmaxf(fmaxf(S[r][0], S[r][1]), fmaxf(S[r][2], S[r][3]));
            bm = fmaxf(bm, __shfl_xor_sync(0xffffffffu, bm, 4, 8));
            bm = fmaxf(bm, __shfl_xor_sync(0xffffffffu, bm, 2, 8));
            bm = fmaxf(bm, __shfl_xor_sync(0xffffffffu, bm, 1, 8));
            float nm = fmaxf(m[r], bm);
            float alpha = expf(m[r] - nm);
            float rs = 0.f;
#pragma unroll
            for (int c = 0; c < 4; c++) { p[r][c] = expf(S[r][c] - nm); rs += p[r][c]; }
            rs += __shfl_xor_sync(0xffffffffu, rs, 4, 8);
            rs += __shfl_xor_sync(0xffffffffu, rs, 2, 8);
            rs += __shfl_xor_sync(0xffffffffu, rs, 1, 8);
            l[r] = l[r] * alpha + rs;
            m[r] = nm;
#pragma unroll
            for (int c = 0; c < 8; c++) O[r][c] *= alpha;
        }
        __syncthreads();                 // everyone done reading K before P overwrites it
#pragma unroll
        for (int r = 0; r < 4; r++)
#pragma unroll
            for (int c = 0; c < 4; c++)
                KPs[(ty*4 + r)*33 + tx*4 + c] = p[r][c];
        __syncthreads();
        // O += P * V
#pragma unroll
        for (int kk = 0; kk < 32; kk++) {
            float pr0 = KPs[(ty*4+0)*33 + kk];
            float pr1 = KPs[(ty*4+1)*33 + kk];
            float pr2 = KPs[(ty*4+2)*33 + kk];
            float pr3 = KPs[(ty*4+3)*33 + kk];
            float4 va = *(const float4*)&Vs[kk][tx*8];
            float4 vb = *(const float4*)&Vs[kk][tx*8+4];
            O[0][0]=fmaf(pr0,va.x,O[0][0]); O[0][1]=fmaf(pr0,va.y,O[0][1]); O[0][2]=fmaf(pr0,va.z,O[0][2]); O[0][3]=fmaf(pr0,va.w,O[0][3]);
            O[0][4]=fmaf(pr0,vb.x,O[0][4]); O[0][5]=fmaf(pr0,vb.y,O[0][5]); O[0][6]=fmaf(pr0,vb.z,O[0][6]); O[0][7]=fmaf(pr0,vb.w,O[0][7]);
            O[1][0]=fmaf(pr1,va.x,O[1][0]); O[1][1]=fmaf(pr1,va.y,O[1][1]); O[1][2]=fmaf(pr1,va.z,O[1][2]); O[1][3]=fmaf(pr1,va.w,O[1][3]);
            O[1][4]=fmaf(pr1,vb.x,O[1][4]); O[1][5]=fmaf(pr1,vb.y,O[1][5]); O[1][6]=fmaf(pr1,vb.z,O[1][6]); O[1][7]=fmaf(pr1,vb.w,O[1][7]);
            O[2][0]=fmaf(pr2,va.x,O[2][0]); O[2][1]=fmaf(pr2,va.y,O[2][1]); O[2][2]=fmaf(pr2,va.z,O[2][2]); O[2][3]=fmaf(pr2,va.w,O[2][3]);
            O[2][4]=fmaf(pr2,vb.x,O[2][4]); O[2][5]=fmaf(pr2,vb.y,O[2][5]); O[2][6]=fmaf(pr2,vb.z,O[2][6]); O[2][7]=fmaf(pr2,vb.w,O[2][7]);
            O[3][0]=fmaf(pr3,va.x,O[3][0]); O[3][1]=fmaf(pr3,va.y,O[3][1]); O[3][2]=fmaf(pr3,va.z,O[3][2]); O[3][3]=fmaf(pr3,va.w,O[3][3]);
            O[3][4]=fmaf(pr3,vb.x,O[3][4]); O[3][5]=fmaf(pr3,vb.y,O[3][5]); O[3][6]=fmaf(pr3,vb.z,O[3][6]); O[3][7]=fmaf(pr3,vb.w,O[3][7]);
        }
        __syncthreads();                 // before next block overwrites K/V
    }

    // finalize: O / l, write attn in [B,T, H*DH] row-major (GEMM-friendly)
    float* ob = g_attn + ((size_t)b * T_ + t0) * DM_ + h * DH_ + tx*8;
#pragma unroll
    for (int r = 0; r < 4; r++) {
        float inv = 1.0f / l[r];
        float4 o1 = make_float4(O[r][0]*inv, O[r][1]*inv, O[r][2]*inv, O[r][3]*inv);
        float4 o2 = make_float4(O[r][4]*inv, O[r][5]*inv, O[r][6]*inv, O[r][7]*inv);
        size_t ro = (size_t)(ty*4 + r) * DM_;
        *(float4*)(ob + ro)     = o1;
        *(float4*)(ob + ro + 4) = o2;
    }
}

// ---------------- Output projection: out = attn*Wo + bo, masked rows -> 0 ----------------
__global__ __launch_bounds__(256) void gemm_out_kernel(
    const float* __restrict__ Wo, const float* __restrict__ bo,
    float* __restrict__ Out, const int* __restrict__ nc)
{
    int row0 = blockIdx.y * 128;
    int col0 = blockIdx.x * 128;
    int b    = row0 / T_;
    int t0   = row0 % T_;
    int Nn   = nc[b];
    int tid  = threadIdx.x;

    if (t0 >= Nn) {   // fully masked tile: d_out is poisoned, write zeros
        float4 z4 = make_float4(0.f,0.f,0.f,0.f);
        for (int i = tid; i < 128*32; i += 256) {
            int r = i >> 5, c4 = (i & 31) << 2;
            *(float4*)(Out + (size_t)(row0 + r)*DM_ + col0 + c4) = z4;
        }
        return;
    }

    __shared__ float As[8][128];
    __shared__ float Bs[8][128];

    int tx   = tid & 15;
    int ty   = tid >> 4;
    int aRow = tid >> 1;
    int aCol = (tid & 1) << 2;
    int bRow = tid >> 5;
    int bCol = (tid & 31) << 2;

    const float* Aptr = g_attn + (size_t)(row0 + aRow) * DM_ + aCol;
    const float* Bptr = Wo + (size_t)bRow * DM_ + col0 + bCol;

    float acc[8][8];
#pragma unroll
    for (int i = 0; i < 8; i++)
#pragma unroll
        for (int j = 0; j < 8; j++) acc[i][j] = 0.f;

    for (int k0 = 0; k0 < DM_; k0 += 8) {
        float4 av = *(const float4*)(Aptr + k0);
        float4 bv4 = *(const float4*)(Bptr + (size_t)k0 * DM_);
        __syncthreads();
        As[aCol+0][aRow] = av.x;
        As[aCol+1][aRow] = av.y;
        As[aCol+2][aRow] = av.z;
        As[aCol+3][aRow] = av.w;
        *(float4*)&Bs[bRow][bCol] = bv4;
        __syncthreads();
#pragma unroll
        for (int kk = 0; kk < 8; kk++) {
            float ar[8], br[8];
            *(float4*)(&ar[0]) = *(const float4*)(&As[kk][ty*8]);
            *(float4*)(&ar[4]) = *(const float4*)(&As[kk][ty*8+4]);
            *(float4*)(&br[0]) = *(const float4*)(&Bs[kk][tx*8]);
            *(float4*)(&br[4]) = *(const float4*)(&Bs[kk][tx*8+4]);
#pragma unroll
            for (int i = 0; i < 8; i++)
#pragma unroll
                for (int j = 0; j < 8; j++)
                    acc[i][j] = fmaf(ar[i], br[j], acc[i][j]);
        }
    }

#pragma unroll
    for (int i = 0; i < 8; i++) {
        int tloc = t0 + ty*8 + i;
        bool ok = (tloc < Nn);
        float* crow = Out + (size_t)(row0 + ty*8 + i) * DM_ + col0 + tx*8;
#pragma unroll
        for (int j = 0; j < 8; j += 4) {
            float4 o;
            o.x = ok ? (acc[i][j+0] + bo[col0 + tx*8 + j+0]) : 0.f;
            o.y = ok ? (acc[i][j+1] + bo[col0 + tx*8 + j+1]) : 0.f;
            o.z = ok ? (acc[i][j+2] + bo[col0 + tx*8 + j+2]) : 0.f;
            o.w = ok ? (acc[i][j+3] + bo[col0 + tx*8 + j+3]) : 0.f;
            *(float4*)(crow + j) = o;
        }
    }
}

// ---------------- launch ----------------
extern "C" void kernel_launch(void* const* d_in, const int* in_sizes, int n_in,
                              void* d_out, int out_size)
{
    const float* x   = (const float*)d_in[0];
    const float* rc  = (const float*)d_in[1];
    const float* rs  = (const float*)d_in[2];
    const float* pk  = (const float*)d_in[3];
    const float* pv  = (const float*)d_in[4];
    const int*   pl  = (const int*)  d_in[5];
    // d_in[6] = valid_new_mask (unused; derived from new_token_counts)
    const int*   nc  = (const int*)  d_in[7];
    const float* Wq  = (const float*)d_in[8];
    const float* bq  = (const float*)d_in[9];
    const float* Wk  = (const float*)d_in[10];
    const float* bk  = (const float*)d_in[11];
    const float* Wv  = (const float*)d_in[12];
    const float* bv  = (const float*)d_in[13];
    const float* Wo  = (const float*)d_in[14];
    const float* bo  = (const float*)d_in[15];
    float* out = (float*)d_out;

    gemm_qkv_kernel<<<dim3(DM_/128, BT_/128, 3), 256>>>(x, Wq, bq, Wk, bk, Wv, bv, nc);
    rope_kernel<<<(BT_*DM_)/256, 256>>>(rc, rs, nc);
    attn_kernel<<<dim3(T_/64, H_, B_), 128>>>(pk, pv, pl, nc);
    gemm_out_kernel<<<dim3(DM_/128, BT_/128), 256>>>(Wo, bo, out, nc);
}

// round 4
// speedup vs baseline: 1.3354x; 1.3354x over previous
#include <cuda_runtime.h>
#include <cuda_bf16.h>
#include <math.h>
#include <stdint.h>

#define B_   8
#define T_   512
#define DM_  1024
#define H_   16
#define DH_  64
#define P_   3584
#define BT_  (B_*T_)     // 4096

// ---------------- scratch (device globals; zero-initialized at load) ----------------
__device__ float g_q  [B_*H_*T_*DH_];
__device__ float g_kn [B_*H_*T_*DH_];
__device__ float g_vn [B_*H_*T_*DH_];
__device__ float g_attn[BT_*DM_];
__device__ __nv_bfloat16 g_x_hi[BT_*DM_];
__device__ __nv_bfloat16 g_x_lo[BT_*DM_];
__device__ __nv_bfloat16 g_at_hi[BT_*DM_];
__device__ __nv_bfloat16 g_at_lo[BT_*DM_];
__device__ __nv_bfloat16 g_wt_hi[4*DM_*DM_];   // transposed weights [n][k], hi part
__device__ __nv_bfloat16 g_wt_lo[4*DM_*DM_];

// ---------------- helpers (sm_80-class ISA only: ldmatrix / mma.sync / cp.async) ----
__device__ __forceinline__ uint32_t smem_u32(const void* p) {
    uint32_t a;
    asm("{ .reg .u64 t; cvta.to.shared.u64 t, %1; cvt.u32.u64 %0, t; }" : "=r"(a) : "l"(p));
    return a;
}

__device__ __forceinline__ void ldm_x4(uint32_t* r, uint32_t addr) {
    asm volatile("ldmatrix.sync.aligned.m8n8.x4.shared.b16 {%0,%1,%2,%3}, [%4];"
        : "=r"(r[0]), "=r"(r[1]), "=r"(r[2]), "=r"(r[3]) : "r"(addr));
}
__device__ __forceinline__ void ldm_x2(uint32_t* r, uint32_t addr) {
    asm volatile("ldmatrix.sync.aligned.m8n8.x2.shared.b16 {%0,%1}, [%2];"
        : "=r"(r[0]), "=r"(r[1]) : "r"(addr));
}
__device__ __forceinline__ void mma16816(float* d, const uint32_t* a, const uint32_t* b) {
    asm volatile("mma.sync.aligned.m16n8k16.row.col.f32.bf16.bf16.f32 "
        "{%0,%1,%2,%3}, {%4,%5,%6,%7}, {%8,%9}, {%0,%1,%2,%3};"
        : "+f"(d[0]), "+f"(d[1]), "+f"(d[2]), "+f"(d[3])
        : "r"(a[0]), "r"(a[1]), "r"(a[2]), "r"(a[3]), "r"(b[0]), "r"(b[1]));
}
__device__ __forceinline__ void cp_async16(uint32_t dst, const void* src) {
    asm volatile("cp.async.cg.shared.global [%0], [%1], 16;" :: "r"(dst), "l"(src));
}

#define KT_          32            // K chunk per stage
#define NCHUNK_      (DM_/KT_)     // 32
#define ROWB_        80            // smem row stride bytes (32 bf16 data + pad), conflict-free mod 128
#define TILE_B_      (128*ROWB_)   // 10240 B per operand tile
#define STAGE_B_     (4*TILE_B_)   // Ahi, Alo, Bhi, Blo
#define SMEM_DYN_    (2*STAGE_B_)  // 81920; also covers Cs (128*132*4 = 67584)

// ---------------- prep: split fp32 -> bf16 hi/lo ----------------
__global__ __launch_bounds__(256) void conv_split_kernel(const float* __restrict__ xsrc, int which)
{
    const float* src = which ? (const float*)g_attn : xsrc;
    __nv_bfloat16* hi = which ? g_at_hi : g_x_hi;
    __nv_bfloat16* lo = which ? g_at_lo : g_x_lo;
    int i4 = blockIdx.x * 256 + threadIdx.x;
    float4 v = ((const float4*)src)[i4];
    __nv_bfloat16 h0 = __float2bfloat16_rn(v.x);
    __nv_bfloat16 h1 = __float2bfloat16_rn(v.y);
    __nv_bfloat16 h2 = __float2bfloat16_rn(v.z);
    __nv_bfloat16 h3 = __float2bfloat16_rn(v.w);
    __nv_bfloat16 l0 = __float2bfloat16_rn(v.x - __bfloat162float(h0));
    __nv_bfloat16 l1 = __float2bfloat16_rn(v.y - __bfloat162float(h1));
    __nv_bfloat16 l2 = __float2bfloat16_rn(v.z - __bfloat162float(h2));
    __nv_bfloat16 l3 = __float2bfloat16_rn(v.w - __bfloat162float(h3));
    ushort4 ho, lw;
    ho.x = __bfloat16_as_ushort(h0); ho.y = __bfloat16_as_ushort(h1);
    ho.z = __bfloat16_as_ushort(h2); ho.w = __bfloat16_as_ushort(h3);
    lw.x = __bfloat16_as_ushort(l0); lw.y = __bfloat16_as_ushort(l1);
    lw.z = __bfloat16_as_ushort(l2); lw.w = __bfloat16_as_ushort(l3);
    ((ushort4*)hi)[i4] = ho;
    ((ushort4*)lo)[i4] = lw;
}

// ---------------- prep: transpose W [k][n] -> Wt [n][k], split hi/lo ----------------
__global__ __launch_bounds__(256) void prep_w_kernel(
    const float* __restrict__ Wq, const float* __restrict__ Wk,
    const float* __restrict__ Wv, const float* __restrict__ Wo)
{
    __shared__ float ts[32][33];
    int zz = blockIdx.z;
    const float* W = (zz == 0) ? Wq : (zz == 1) ? Wk : (zz == 2) ? Wv : Wo;
    size_t base = (size_t)zz * DM_ * DM_;
    int n0 = blockIdx.x * 32, k0 = blockIdx.y * 32;
    int tx = threadIdx.x & 31, ty8 = threadIdx.x >> 5;
    for (int i = ty8; i < 32; i += 8)
        ts[i][tx] = W[(size_t)(k0 + i) * DM_ + n0 + tx];
    __syncthreads();
    for (int i = ty8; i < 32; i += 8) {
        float v = ts[tx][i];                       // W[k0+tx][n0+i]
        __nv_bfloat16 h = __float2bfloat16_rn(v);
        __nv_bfloat16 l = __float2bfloat16_rn(v - __bfloat162float(h));
        size_t off = base + (size_t)(n0 + i) * DM_ + k0 + tx;
        g_wt_hi[off] = h;
        g_wt_lo[off] = l;
    }
}

// ---------------- mma.sync GEMM: C[128x128] = A[128xK] * Wt[128xK]^T, hi/lo 3-pass ----
// mode 0: A = x (hi/lo), z = blockIdx.z in {Q,K,V}; epilogue = bias + RoPE + mask -> g_q/g_kn/g_vn
// mode 1: A = attn (hi/lo), z = 3 (Wo); epilogue = bias + mask -> Out
__global__ void __launch_bounds__(256, 1) mma_gemm_kernel(
    const float* __restrict__ rcos, const float* __restrict__ rsin,
    const float* __restrict__ bq, const float* __restrict__ bk,
    const float* __restrict__ bv, const float* __restrict__ bo,
    float* __restrict__ Out, const int* __restrict__ nc, int mode)
{
    int z    = (mode == 0) ? (int)blockIdx.z : 3;
    int row0 = blockIdx.y * 128;
    int col0 = blockIdx.x * 128;
    int b    = row0 >> 9;
    int t0b  = row0 & 511;
    int Nn   = nc[b];
    int tid  = threadIdx.x;

    if (t0b >= Nn) {                   // fully masked row block
        if (mode == 1) {               // d_out is poisoned: must write zeros
            float4 z4 = make_float4(0.f, 0.f, 0.f, 0.f);
            for (int i = tid; i < 128 * 32; i += 256) {
                int r = i >> 5, c4 = (i & 31) << 2;
                *(float4*)(Out + (size_t)(row0 + r) * DM_ + col0 + c4) = z4;
            }
        }
        return;
    }

    const __nv_bfloat16* Ahi = (mode == 0) ? g_x_hi : g_at_hi;
    const __nv_bfloat16* Alo = (mode == 0) ? g_x_lo : g_at_lo;
    const __nv_bfloat16* Bhi = g_wt_hi + (size_t)z * DM_ * DM_;
    const __nv_bfloat16* Blo = g_wt_lo + (size_t)z * DM_ * DM_;

    extern __shared__ __align__(128) char smem[];
    uint32_t sbase = smem_u32(smem);

    int lane = tid & 31;
    int wid  = tid >> 5;
    int wm   = wid >> 2;               // 0..1  (64 rows each)
    int wn   = wid & 3;                // 0..3  (32 cols each)

    float acc[4][4][4];
#pragma unroll
    for (int i = 0; i < 4; i++)
#pragma unroll
        for (int j = 0; j < 4; j++)
#pragma unroll
            for (int q = 0; q < 4; q++) acc[i][j][q] = 0.f;

    // per-thread ldmatrix address components (bf16-element units within tile)
    int aRow = wm * 64 + (lane & 15);
    int aCol = (lane >> 4) << 3;               // 0 or 8
    int bRow = wn * 32 + (lane & 7);
    int bCol = ((lane >> 3) & 1) << 3;         // 0 or 8

    // ---- cp.async double-buffered pipeline ----
#define LOAD_STAGE(ii) do {                                                     \
        int _i = (ii);                                                          \
        int _s = _i & 1;                                                        \
        int _k0 = _i * KT_;                                                     \
        uint32_t _sd = sbase + _s * STAGE_B_;                                   \
        _Pragma("unroll")                                                       \
        for (int _j = 0; _j < 8; _j++) {                                        \
            int _idx  = tid + _j * 256;                                         \
            int _tile = _idx >> 9;                                              \
            int _r    = (_idx >> 2) & 127;                                      \
            int _c    = _idx & 3;                                               \
            const __nv_bfloat16* _gp =                                          \
                (_tile == 0) ? Ahi : (_tile == 1) ? Alo :                       \
                (_tile == 2) ? Bhi : Blo;                                       \
            int _grow = (_tile < 2) ? (row0 + _r) : (col0 + _r);                \
            cp_async16(_sd + _tile * TILE_B_ + _r * ROWB_ + _c * 16,            \
                       _gp + (size_t)_grow * DM_ + _k0 + _c * 8);               \
        }                                                                       \
        asm volatile("cp.async.commit_group;" ::: "memory");                    \
    } while (0)

    LOAD_STAGE(0);
    for (int i = 0; i < NCHUNK_; i++) {
        if (i + 1 < NCHUNK_) {
            LOAD_STAGE(i + 1);
            asm volatile("cp.async.wait_group 1;" ::: "memory");
        } else {
            asm volatile("cp.async.wait_group 0;" ::: "memory");
        }
        __syncthreads();

        uint32_t st = sbase + (i & 1) * STAGE_B_;
#pragma unroll
        for (int kk = 0; kk < KT_; kk += 16) {
            uint32_t Ah[4][4], Al[4][4], Bh[4][2], Bl[4][2];
#pragma unroll
            for (int fm = 0; fm < 4; fm++) {
                uint32_t off = (uint32_t)((aRow + fm * 16) * ROWB_ + (kk + aCol) * 2);
                ldm_x4(Ah[fm], st + 0 * TILE_B_ + off);
                ldm_x4(Al[fm], st + 1 * TILE_B_ + off);
            }
#pragma unroll
            for (int fn = 0; fn < 4; fn++) {
                uint32_t off = (uint32_t)((bRow + fn * 8) * ROWB_ + (kk + bCol) * 2);
                ldm_x2(Bh[fn], st + 2 * TILE_B_ + off);
                ldm_x2(Bl[fn], st + 3 * TILE_B_ + off);
            }
#pragma unroll
            for (int fm = 0; fm < 4; fm++)
#pragma unroll
                for (int fn = 0; fn < 4; fn++) {
                    mma16816(acc[fm][fn], Ah[fm], Bh[fn]);
                    mma16816(acc[fm][fn], Ah[fm], Bl[fn]);
                    mma16816(acc[fm][fn], Al[fm], Bh[fn]);
                }
        }
        __syncthreads();
    }

    // ---- store accumulators to smem fp32 tile (reuses stage memory) ----
    float* Cs = (float*)smem;                  // [128][132]
#pragma unroll
    for (int fm = 0; fm < 4; fm++)
#pragma unroll
        for (int fn = 0; fn < 4; fn++) {
            int m = wm * 64 + fm * 16 + (lane >> 2);
            int n = wn * 32 + fn * 8 + ((lane & 3) << 1);
            *(float2*)&Cs[m * 132 + n]       = make_float2(acc[fm][fn][0], acc[fm][fn][1]);
            *(float2*)&Cs[(m + 8) * 132 + n] = make_float2(acc[fm][fn][2], acc[fm][fn][3]);
        }
    __syncthreads();

    // ---- fused epilogue ----
    if (tid < 128) {
        int r = tid;
        int m = row0 + r;
        int t = m & 511;
        bool valid = (t < Nn);
        const float* Cr = Cs + r * 132;
        if (mode == 1) {
            float* dst = Out + (size_t)m * DM_ + col0;
#pragma unroll 8
            for (int c = 0; c < 128; c += 4) {
                float4 o;
                o.x = valid ? Cr[c+0] + bo[col0+c+0] : 0.f;
                o.y = valid ? Cr[c+1] + bo[col0+c+1] : 0.f;
                o.z = valid ? Cr[c+2] + bo[col0+c+2] : 0.f;
                o.w = valid ? Cr[c+3] + bo[col0+c+3] : 0.f;
                *(float4*)(dst + c) = o;
            }
        } else {
            float* dstbase = (z == 0) ? g_q : (z == 1) ? g_kn : g_vn;
            const float* bias = (z == 0) ? bq : (z == 1) ? bk : bv;
            for (int hh = 0; hh < 2; hh++) {
                float v[64], o[64];
#pragma unroll
                for (int j = 0; j < 64; j++)
                    v[j] = Cr[hh * 64 + j] + bias[col0 + hh * 64 + j];
                if (z < 2) {   // RoPE
#pragma unroll
                    for (int d = 0; d < 32; d++) {
                        float cc = rcos[(t << 6) + d];
                        float ss = rsin[(t << 6) + d];
                        o[d]      = v[d] * cc - v[d + 32] * ss;
                        o[d + 32] = v[d + 32] * cc + v[d] * ss;
                    }
                    if (z == 0) {
#pragma unroll
                        for (int j = 0; j < 64; j++) o[j] *= 0.125f;  // fold 1/sqrt(DH)
                    }
                } else {
#pragma unroll
                    for (int j = 0; j < 64; j++) o[j] = v[j];
                }
                if (!valid) {
#pragma unroll
                    for (int j = 0; j < 64; j++) o[j] = 0.f;
                }
                int h = (col0 >> 6) + hh;
                float* dst = dstbase + (((size_t)b * H_ + h) * T_ + t) * DH_;
#pragma unroll
                for (int j = 0; j < 64; j += 4)
                    *(float4*)(dst + j) = make_float4(o[j], o[j+1], o[j+2], o[j+3]);
            }
        }
    }
}

// ---------------- Flash attention (unchanged from passing R2 version) ----------------
__global__ __launch_bounds__(128) void attn_kernel(
    const float* __restrict__ past_k, const float* __restrict__ past_v,
    const int* __restrict__ plen, const int* __restrict__ nc)
{
    __shared__ float Qs[64][65];
    __shared__ float KPs[2112];
    __shared__ float Vs[32][68];

    int b  = blockIdx.z;
    int h  = blockIdx.y;
    int t0 = blockIdx.x * 64;
    int Nn = nc[b];
    if (t0 >= Nn) return;
    int Tp = plen[b];
    if (Tp < 0) Tp = 0; if (Tp > P_) Tp = P_;
    int Ltot = Tp + Nn;

    int tid = threadIdx.x;
    int tx  = tid & 7;
    int ty  = tid >> 3;

    size_t bh = (size_t)b * H_ + h;
    const float* qbase = g_q  + (bh * T_ + t0) * DH_;
    const float* knb   = g_kn + bh * T_ * DH_;
    const float* vnb   = g_vn + bh * T_ * DH_;
    const float* pkb   = past_k + bh * P_ * DH_;
    const float* pvb   = past_v + bh * P_ * DH_;

    for (int i = tid; i < 64 * 16; i += 128) {
        int r = i >> 4, c4 = (i & 15) << 2;
        float4 v = *(const float4*)(qbase + r * DH_ + c4);
        Qs[r][c4+0] = v.x; Qs[r][c4+1] = v.y; Qs[r][c4+2] = v.z; Qs[r][c4+3] = v.w;
    }

    float m[4], l[4], O[4][8];
#pragma unroll
    for (int r = 0; r < 4; r++) {
        m[r] = -1e30f; l[r] = 0.f;
#pragma unroll
        for (int c = 0; c < 8; c++) O[r][c] = 0.f;
    }
    __syncthreads();

    for (int j0 = 0; j0 < Ltot; j0 += 32) {
        for (int i = tid; i < 32 * 16; i += 128) {
            int r = i >> 4, c4 = (i & 15) << 2;
            int key = j0 + r;
            float4 kv = make_float4(0.f,0.f,0.f,0.f);
            float4 vv = make_float4(0.f,0.f,0.f,0.f);
            if (key < Tp) {
                kv = *(const float4*)(pkb + (size_t)key*DH_ + c4);
                vv = *(const float4*)(pvb + (size_t)key*DH_ + c4);
            } else if (key >= P_ && key < Ltot) {
                kv = *(const float4*)(knb + (size_t)(key - P_)*DH_ + c4);
                vv = *(const float4*)(vnb + (size_t)(key - P_)*DH_ + c4);
            }
            KPs[r*65 + c4+0] = kv.x; KPs[r*65 + c4+1] = kv.y;
            KPs[r*65 + c4+2] = kv.z; KPs[r*65 + c4+3] = kv.w;
            *(float4*)&Vs[r][c4] = vv;
        }
        __syncthreads();

        float S[4][4];
#pragma unroll
        for (int r = 0; r < 4; r++)
#pragma unroll
            for (int c = 0; c < 4; c++) S[r][c] = 0.f;
#pragma unroll 4
        for (int d = 0; d < 64; d++) {
            float q0 = Qs[ty*4+0][d], q1 = Qs[ty*4+1][d];
            float q2 = Qs[ty*4+2][d], q3 = Qs[ty*4+3][d];
            float k0 = KPs[(tx*4+0)*65 + d], k1 = KPs[(tx*4+1)*65 + d];
            float k2 = KPs[(tx*4+2)*65 + d], k3 = KPs[(tx*4+3)*65 + d];
            S[0][0]=fmaf(q0,k0,S[0][0]); S[0][1]=fmaf(q0,k1,S[0][1]); S[0][2]=fmaf(q0,k2,S[0][2]); S[0][3]=fmaf(q0,k3,S[0][3]);
            S[1][0]=fmaf(q1,k0,S[1][0]); S[1][1]=fmaf(q1,k1,S[1][1]); S[1][2]=fmaf(q1,k2,S[1][2]); S[1][3]=fmaf(q1,k3,S[1][3]);
            S[2][0]=fmaf(q2,k0,S[2][0]); S[2][1]=fmaf(q2,k1,S[2][1]); S[2][2]=fmaf(q2,k2,S[2][2]); S[2][3]=fmaf(q2,k3,S[2][3]);
            S[3][0]=fmaf(q3,k0,S[3][0]); S[3][1]=fmaf(q3,k1,S[3][1]); S[3][2]=fmaf(q3,k2,S[3][2]); S[3][3]=fmaf(q3,k3,S[3][3]);
        }
#pragma unroll
        for (int c = 0; c < 4; c++) {
            if (j0 + tx*4 + c >= Ltot) {
#pragma unroll
                for (int r = 0; r < 4; r++) S[r][c] = -1e9f;
            }
        }
        float p[4][4];
#pragma unroll
        for (int r = 0; r < 4; r++) {
            float bm = fmaxf(fmaxf(S[r][0], S[r][1]), fmaxf(S[r][2], S[r][3]));
            bm = fmaxf(bm, __shfl_xor_sync(0xffffffffu, bm, 4, 8));
            bm = fmaxf(bm, __shfl_xor_sync(0xffffffffu, bm, 2, 8));
            bm = fmaxf(bm, __shfl_xor_sync(0xffffffffu, bm, 1, 8));
            float nm = fmaxf(m[r], bm);
            float alpha = expf(m[r] - nm);
            float rs = 0.f;
#pragma unroll
            for (int c = 0; c < 4; c++) { p[r][c] = expf(S[r][c] - nm); rs += p[r][c]; }
            rs += __shfl_xor_sync(0xffffffffu, rs, 4, 8);
            rs += __shfl_xor_sync(0xffffffffu, rs, 2, 8);
            rs += __shfl_xor_sync(0xffffffffu, rs, 1, 8);
            l[r] = l[r] * alpha + rs;
            m[r] = nm;
#pragma unroll
            for (int c = 0; c < 8; c++) O[r][c] *= alpha;
        }
        __syncthreads();
#pragma unroll
        for (int r = 0; r < 4; r++)
#pragma unroll
            for (int c = 0; c < 4; c++)
                KPs[(ty*4 + r)*33 + tx*4 + c] = p[r][c];
        __syncthreads();
#pragma unroll
        for (int kk = 0; kk < 32; kk++) {
            float pr0 = KPs[(ty*4+0)*33 + kk];
            float pr1 = KPs[(ty*4+1)*33 + kk];
            float pr2 = KPs[(ty*4+2)*33 + kk];
            float pr3 = KPs[(ty*4+3)*33 + kk];
            float4 va = *(const float4*)&Vs[kk][tx*8];
            float4 vb = *(const float4*)&Vs[kk][tx*8+4];
            O[0][0]=fmaf(pr0,va.x,O[0][0]); O[0][1]=fmaf(pr0,va.y,O[0][1]); O[0][2]=fmaf(pr0,va.z,O[0][2]); O[0][3]=fmaf(pr0,va.w,O[0][3]);
            O[0][4]=fmaf(pr0,vb.x,O[0][4]); O[0][5]=fmaf(pr0,vb.y,O[0][5]); O[0][6]=fmaf(pr0,vb.z,O[0][6]); O[0][7]=fmaf(pr0,vb.w,O[0][7]);
            O[1][0]=fmaf(pr1,va.x,O[1][0]); O[1][1]=fmaf(pr1,va.y,O[1][1]); O[1][2]=fmaf(pr1,va.z,O[1][2]); O[1][3]=fmaf(pr1,va.w,O[1][3]);
            O[1][4]=fmaf(pr1,vb.x,O[1][4]); O[1][5]=fmaf(pr1,vb.y,O[1][5]); O[1][6]=fmaf(pr1,vb.z,O[1][6]); O[1][7]=fmaf(pr1,vb.w,O[1][7]);
            O[2][0]=fmaf(pr2,va.x,O[2][0]); O[2][1]=fmaf(pr2,va.y,O[2][1]); O[2][2]=fmaf(pr2,va.z,O[2][2]); O[2][3]=fmaf(pr2,va.w,O[2][3]);
            O[2][4]=fmaf(pr2,vb.x,O[2][4]); O[2][5]=fmaf(pr2,vb.y,O[2][5]); O[2][6]=fmaf(pr2,vb.z,O[2][6]); O[2][7]=fmaf(pr2,vb.w,O[2][7]);
            O[3][0]=fmaf(pr3,va.x,O[3][0]); O[3][1]=fmaf(pr3,va.y,O[3][1]); O[3][2]=fmaf(pr3,va.z,O[3][2]); O[3][3]=fmaf(pr3,va.w,O[3][3]);
            O[3][4]=fmaf(pr3,vb.x,O[3][4]); O[3][5]=fmaf(pr3,vb.y,O[3][5]); O[3][6]=fmaf(pr3,vb.z,O[3][6]); O[3][7]=fmaf(pr3,vb.w,O[3][7]);
        }
        __syncthreads();
    }

    float* ob = g_attn + ((size_t)b * T_ + t0) * DM_ + h * DH_ + tx*8;
#pragma unroll
    for (int r = 0; r < 4; r++) {
        float inv = 1.0f / l[r];
        float4 o1 = make_float4(O[r][0]*inv, O[r][1]*inv, O[r][2]*inv, O[r][3]*inv);
        float4 o2 = make_float4(O[r][4]*inv, O[r][5]*inv, O[r][6]*inv, O[r][7]*inv);
        size_t ro = (size_t)(ty*4 + r) * DM_;
        *(float4*)(ob + ro)     = o1;
        *(float4*)(ob + ro + 4) = o2;
    }
}

// ---------------- launch ----------------
extern "C" void kernel_launch(void* const* d_in, const int* in_sizes, int n_in,
                              void* d_out, int out_size)
{
    const float* x   = (const float*)d_in[0];
    const float* rc  = (const float*)d_in[1];
    const float* rs  = (const float*)d_in[2];
    const float* pk  = (const float*)d_in[3];
    const float* pv  = (const float*)d_in[4];
    const int*   pl  = (const int*)  d_in[5];
    const int*   nc  = (const int*)  d_in[7];
    const float* Wq  = (const float*)d_in[8];
    const float* bq  = (const float*)d_in[9];
    const float* Wk  = (const float*)d_in[10];
    const float* bk  = (const float*)d_in[11];
    const float* Wv  = (const float*)d_in[12];
    const float* bv  = (const float*)d_in[13];
    const float* Wo  = (const float*)d_in[14];
    const float* bo  = (const float*)d_in[15];
    float* out = (float*)d_out;

    cudaFuncSetAttribute(mma_gemm_kernel,
                         cudaFuncAttributeMaxDynamicSharedMemorySize, SMEM_DYN_);

    conv_split_kernel<<<(BT_*DM_)/(4*256), 256>>>(x, 0);
    prep_w_kernel<<<dim3(32, 32, 4), 256>>>(Wq, Wk, Wv, Wo);
    mma_gemm_kernel<<<dim3(8, 32, 3), 256, SMEM_DYN_>>>(rc, rs, bq, bk, bv, bo, out, nc, 0);
    attn_kernel<<<dim3(T_/64, H_, B_), 128>>>(pk, pv, pl, nc);
    conv_split_kernel<<<(BT_*DM_)/(4*256), 256>>>(x, 1);
    mma_gemm_kernel<<<dim3(8, 32, 1), 256, SMEM_DYN_>>>(rc, rs, bq, bk, bv, bo, out, nc, 1);
}

// round 5
// speedup vs baseline: 3.3998x; 2.5459x over previous
#include <cuda_runtime.h>
#include <cuda_bf16.h>
#include <math.h>
#include <stdint.h>

#define B_   8
#define T_   512
#define DM_  1024
#define H_   16
#define DH_  64
#define P_   3584
#define BT_  (B_*T_)       // 4096
#define BHTD_ (B_*H_*T_*DH_)   // 4194304
#define BHPD_ (B_*H_*P_*DH_)   // 29360128
#define QSC_ 0.18033688011112042f   // 0.125 * log2(e): scores in log2 units

// ---------------- scratch (device globals; zero-initialized at load) ----------------
__device__ __nv_bfloat16 g_x_hi[BT_*DM_];
__device__ __nv_bfloat16 g_x_lo[BT_*DM_];
__device__ __nv_bfloat16 g_at_hi[BT_*DM_];
__device__ __nv_bfloat16 g_at_lo[BT_*DM_];
__device__ __nv_bfloat16 g_wt_hi[4*DM_*DM_];
__device__ __nv_bfloat16 g_wt_lo[4*DM_*DM_];
// head-major [B,H,T,DH] bf16 hi/lo (padded +64 rows for block-overrun reads)
__device__ __nv_bfloat16 g_qh [BHTD_+64*DH_];
__device__ __nv_bfloat16 g_ql [BHTD_+64*DH_];
__device__ __nv_bfloat16 g_knh[BHTD_+64*DH_];
__device__ __nv_bfloat16 g_knl[BHTD_+64*DH_];
__device__ __nv_bfloat16 g_vnh[BHTD_+64*DH_];
__device__ __nv_bfloat16 g_vnl[BHTD_+64*DH_];
// past K/V bf16 hi/lo [B,H,P,DH]
__device__ __nv_bfloat16 g_pkh[BHPD_];
__device__ __nv_bfloat16 g_pkl[BHPD_];
__device__ __nv_bfloat16 g_pvh[BHPD_];
__device__ __nv_bfloat16 g_pvl[BHPD_];

// ---------------- helpers ----------------
__device__ __forceinline__ uint32_t smem_u32(const void* p) {
    uint32_t a;
    asm("{ .reg .u64 t; cvta.to.shared.u64 t, %1; cvt.u32.u64 %0, t; }" : "=r"(a) : "l"(p));
    return a;
}
__device__ __forceinline__ void ldm_x4(uint32_t* r, uint32_t addr) {
    asm volatile("ldmatrix.sync.aligned.m8n8.x4.shared.b16 {%0,%1,%2,%3}, [%4];"
        : "=r"(r[0]), "=r"(r[1]), "=r"(r[2]), "=r"(r[3]) : "r"(addr));
}
__device__ __forceinline__ void ldm_x2(uint32_t* r, uint32_t addr) {
    asm volatile("ldmatrix.sync.aligned.m8n8.x2.shared.b16 {%0,%1}, [%2];"
        : "=r"(r[0]), "=r"(r[1]) : "r"(addr));
}
__device__ __forceinline__ void ldm_x2t(uint32_t* r, uint32_t addr) {
    asm volatile("ldmatrix.sync.aligned.m8n8.x2.trans.shared.b16 {%0,%1}, [%2];"
        : "=r"(r[0]), "=r"(r[1]) : "r"(addr));
}
__device__ __forceinline__ void mma16816(float* d, const uint32_t* a, const uint32_t* b) {
    asm volatile("mma.sync.aligned.m16n8k16.row.col.f32.bf16.bf16.f32 "
        "{%0,%1,%2,%3}, {%4,%5,%6,%7}, {%8,%9}, {%0,%1,%2,%3};"
        : "+f"(d[0]), "+f"(d[1]), "+f"(d[2]), "+f"(d[3])
        : "r"(a[0]), "r"(a[1]), "r"(a[2]), "r"(a[3]), "r"(b[0]), "r"(b[1]));
}
__device__ __forceinline__ void cp_async16(uint32_t dst, const void* src) {
    asm volatile("cp.async.cg.shared.global [%0], [%1], 16;" :: "r"(dst), "l"(src));
}
__device__ __forceinline__ float ex2f(float x) {
    float r; asm("ex2.approx.ftz.f32 %0, %1;" : "=f"(r) : "f"(x)); return r;
}
__device__ __forceinline__ uint32_t packbf(float lo, float hi) {
    uint32_t r; asm("cvt.rn.bf16x2.f32 %0, %1, %2;" : "=r"(r) : "f"(hi), "f"(lo)); return r;
}
__device__ __forceinline__ float bflo(uint32_t u){ return __uint_as_float(u << 16); }
__device__ __forceinline__ float bfhi(uint32_t u){ return __uint_as_float(u & 0xffff0000u); }

// ---------------- prep: split x fp32 -> bf16 hi/lo ----------------
__global__ __launch_bounds__(256) void conv_split_kernel(const float* __restrict__ src)
{
    int i4 = blockIdx.x * 256 + threadIdx.x;
    float4 v = ((const float4*)src)[i4];
    __nv_bfloat16 h0 = __float2bfloat16_rn(v.x), h1 = __float2bfloat16_rn(v.y);
    __nv_bfloat16 h2 = __float2bfloat16_rn(v.z), h3 = __float2bfloat16_rn(v.w);
    __nv_bfloat16 l0 = __float2bfloat16_rn(v.x - __bfloat162float(h0));
    __nv_bfloat16 l1 = __float2bfloat16_rn(v.y - __bfloat162float(h1));
    __nv_bfloat16 l2 = __float2bfloat16_rn(v.z - __bfloat162float(h2));
    __nv_bfloat16 l3 = __float2bfloat16_rn(v.w - __bfloat162float(h3));
    ushort4 ho, lw;
    ho.x = __bfloat16_as_ushort(h0); ho.y = __bfloat16_as_ushort(h1);
    ho.z = __bfloat16_as_ushort(h2); ho.w = __bfloat16_as_ushort(h3);
    lw.x = __bfloat16_as_ushort(l0); lw.y = __bfloat16_as_ushort(l1);
    lw.z = __bfloat16_as_ushort(l2); lw.w = __bfloat16_as_ushort(l3);
    ((ushort4*)g_x_hi)[i4] = ho;
    ((ushort4*)g_x_lo)[i4] = lw;
}

// ---------------- prep: transpose W [k][n] -> Wt [n][k], split hi/lo ----------------
__global__ __launch_bounds__(256) void prep_w_kernel(
    const float* __restrict__ Wq, const float* __restrict__ Wk,
    const float* __restrict__ Wv, const float* __restrict__ Wo)
{
    __shared__ float ts[32][33];
    int zz = blockIdx.z;
    const float* W = (zz == 0) ? Wq : (zz == 1) ? Wk : (zz == 2) ? Wv : Wo;
    size_t base = (size_t)zz * DM_ * DM_;
    int n0 = blockIdx.x * 32, k0 = blockIdx.y * 32;
    int tx = threadIdx.x & 31, ty8 = threadIdx.x >> 5;
    for (int i = ty8; i < 32; i += 8)
        ts[i][tx] = W[(size_t)(k0 + i) * DM_ + n0 + tx];
    __syncthreads();
    for (int i = ty8; i < 32; i += 8) {
        float v = ts[tx][i];
        __nv_bfloat16 h = __float2bfloat16_rn(v);
        __nv_bfloat16 l = __float2bfloat16_rn(v - __bfloat162float(h));
        size_t off = base + (size_t)(n0 + i) * DM_ + k0 + tx;
        g_wt_hi[off] = h;
        g_wt_lo[off] = l;
    }
}

// ---------------- prep: past K/V fp32 -> bf16 hi/lo (only rows < Tp) -------------
__global__ __launch_bounds__(256) void prep_past_kernel(
    const float* __restrict__ pk, const float* __restrict__ pv,
    const int* __restrict__ plen)
{
    int bh = blockIdx.y;
    int b  = bh >> 4;
    int Tp = plen[b]; Tp = Tp < 0 ? 0 : (Tp > P_ ? P_ : Tp);
    int i4 = blockIdx.x * 256 + threadIdx.x;     // float4 index within [P*DH/4)
    int key = i4 >> 4;                            // 16 float4 per key row
    if (key >= Tp) return;
    size_t off = (size_t)bh * (P_*DH_) + (size_t)i4 * 4;
    float4 kv = *(const float4*)(pk + off);
    float4 vv = *(const float4*)(pv + off);
#define SPLIT4(V, HI, LO) do {                                                  \
        __nv_bfloat16 h0=__float2bfloat16_rn(V.x), h1=__float2bfloat16_rn(V.y); \
        __nv_bfloat16 h2=__float2bfloat16_rn(V.z), h3=__float2bfloat16_rn(V.w); \
        ushort4 hv, lv;                                                          \
        hv.x=__bfloat16_as_ushort(h0); hv.y=__bfloat16_as_ushort(h1);            \
        hv.z=__bfloat16_as_ushort(h2); hv.w=__bfloat16_as_ushort(h3);            \
        lv.x=__bfloat16_as_ushort(__float2bfloat16_rn(V.x-__bfloat162float(h0)));\
        lv.y=__bfloat16_as_ushort(__float2bfloat16_rn(V.y-__bfloat162float(h1)));\
        lv.z=__bfloat16_as_ushort(__float2bfloat16_rn(V.z-__bfloat162float(h2)));\
        lv.w=__bfloat16_as_ushort(__float2bfloat16_rn(V.w-__bfloat162float(h3)));\
        *(ushort4*)(HI + off) = hv; *(ushort4*)(LO + off) = lv;                  \
    } while(0)
    SPLIT4(kv, g_pkh, g_pkl);
    SPLIT4(vv, g_pvh, g_pvl);
#undef SPLIT4
}

// ---------------- mma.sync GEMM (as R4) with bf16 hi/lo epilogue outputs ---------
#define KT_          32
#define NCHUNK_      (DM_/KT_)
#define ROWB_        80
#define TILE_B_      (128*ROWB_)
#define STAGE_B_     (4*TILE_B_)
#define SMEM_GEMM_   (2*STAGE_B_)

__global__ void __launch_bounds__(256, 1) mma_gemm_kernel(
    const float* __restrict__ rcos, const float* __restrict__ rsin,
    const float* __restrict__ bq, const float* __restrict__ bk,
    const float* __restrict__ bv, const float* __restrict__ bo,
    float* __restrict__ Out, const int* __restrict__ nc, int mode)
{
    int z    = (mode == 0) ? (int)blockIdx.z : 3;
    int row0 = blockIdx.y * 128;
    int col0 = blockIdx.x * 128;
    int b    = row0 >> 9;
    int t0b  = row0 & 511;
    int Nn   = nc[b];
    int tid  = threadIdx.x;

    if (t0b >= Nn) {
        if (mode == 1) {
            float4 z4 = make_float4(0.f, 0.f, 0.f, 0.f);
            for (int i = tid; i < 128 * 32; i += 256) {
                int r = i >> 5, c4 = (i & 31) << 2;
                *(float4*)(Out + (size_t)(row0 + r) * DM_ + col0 + c4) = z4;
            }
        }
        return;
    }

    const __nv_bfloat16* Ahi = (mode == 0) ? g_x_hi : g_at_hi;
    const __nv_bfloat16* Alo = (mode == 0) ? g_x_lo : g_at_lo;
    const __nv_bfloat16* Bhi = g_wt_hi + (size_t)z * DM_ * DM_;
    const __nv_bfloat16* Blo = g_wt_lo + (size_t)z * DM_ * DM_;

    extern __shared__ __align__(128) char smem[];
    uint32_t sbase = smem_u32(smem);

    int lane = tid & 31;
    int wid  = tid >> 5;
    int wm   = wid >> 2;
    int wn   = wid & 3;

    float acc[4][4][4];
#pragma unroll
    for (int i = 0; i < 4; i++)
#pragma unroll
        for (int j = 0; j < 4; j++)
#pragma unroll
            for (int q = 0; q < 4; q++) acc[i][j][q] = 0.f;

    int aRow = wm * 64 + (lane & 15);
    int aCol = (lane >> 4) << 3;
    int bRow = wn * 32 + (lane & 7);
    int bCol = ((lane >> 3) & 1) << 3;

#define LOAD_STAGE(ii) do {                                                     \
        int _i = (ii);                                                          \
        int _s = _i & 1;                                                        \
        int _k0 = _i * KT_;                                                     \
        uint32_t _sd = sbase + _s * STAGE_B_;                                   \
        _Pragma("unroll")                                                       \
        for (int _j = 0; _j < 8; _j++) {                                        \
            int _idx  = tid + _j * 256;                                         \
            int _tile = _idx >> 9;                                              \
            int _r    = (_idx >> 2) & 127;                                      \
            int _c    = _idx & 3;                                               \
            const __nv_bfloat16* _gp =                                          \
                (_tile == 0) ? Ahi : (_tile == 1) ? Alo :                       \
                (_tile == 2) ? Bhi : Blo;                                       \
            int _grow = (_tile < 2) ? (row0 + _r) : (col0 + _r);                \
            cp_async16(_sd + _tile * TILE_B_ + _r * ROWB_ + _c * 16,            \
                       _gp + (size_t)_grow * DM_ + _k0 + _c * 8);               \
        }                                                                       \
        asm volatile("cp.async.commit_group;" ::: "memory");                    \
    } while (0)

    LOAD_STAGE(0);
    for (int i = 0; i < NCHUNK_; i++) {
        if (i + 1 < NCHUNK_) {
            LOAD_STAGE(i + 1);
            asm volatile("cp.async.wait_group 1;" ::: "memory");
        } else {
            asm volatile("cp.async.wait_group 0;" ::: "memory");
        }
        __syncthreads();

        uint32_t st = sbase + (i & 1) * STAGE_B_;
#pragma unroll
        for (int kk = 0; kk < KT_; kk += 16) {
            uint32_t Ah[4][4], Al[4][4], Bh[4][2], Bl[4][2];
#pragma unroll
            for (int fm = 0; fm < 4; fm++) {
                uint32_t off = (uint32_t)((aRow + fm * 16) * ROWB_ + (kk + aCol) * 2);
                ldm_x4(Ah[fm], st + 0 * TILE_B_ + off);
                ldm_x4(Al[fm], st + 1 * TILE_B_ + off);
            }
#pragma unroll
            for (int fn = 0; fn < 4; fn++) {
                uint32_t off = (uint32_t)((bRow + fn * 8) * ROWB_ + (kk + bCol) * 2);
                ldm_x2(Bh[fn], st + 2 * TILE_B_ + off);
                ldm_x2(Bl[fn], st + 3 * TILE_B_ + off);
            }
#pragma unroll
            for (int fm = 0; fm < 4; fm++)
#pragma unroll
                for (int fn = 0; fn < 4; fn++) {
                    mma16816(acc[fm][fn], Ah[fm], Bh[fn]);
                    mma16816(acc[fm][fn], Ah[fm], Bl[fn]);
                    mma16816(acc[fm][fn], Al[fm], Bh[fn]);
                }
        }
        __syncthreads();
    }
#undef LOAD_STAGE

    float* Cs = (float*)smem;                  // [128][132]
#pragma unroll
    for (int fm = 0; fm < 4; fm++)
#pragma unroll
        for (int fn = 0; fn < 4; fn++) {
            int m = wm * 64 + fm * 16 + (lane >> 2);
            int n = wn * 32 + fn * 8 + ((lane & 3) << 1);
            *(float2*)&Cs[m * 132 + n]       = make_float2(acc[fm][fn][0], acc[fm][fn][1]);
            *(float2*)&Cs[(m + 8) * 132 + n] = make_float2(acc[fm][fn][2], acc[fm][fn][3]);
        }
    __syncthreads();

    if (tid < 128) {
        int r = tid;
        int m = row0 + r;
        int t = m & 511;
        bool valid = (t < Nn);
        const float* Cr = Cs + r * 132;
        if (mode == 1) {
            float* dst = Out + (size_t)m * DM_ + col0;
#pragma unroll 8
            for (int c = 0; c < 128; c += 4) {
                float4 o;
                o.x = valid ? Cr[c+0] + bo[col0+c+0] : 0.f;
                o.y = valid ? Cr[c+1] + bo[col0+c+1] : 0.f;
                o.z = valid ? Cr[c+2] + bo[col0+c+2] : 0.f;
                o.w = valid ? Cr[c+3] + bo[col0+c+3] : 0.f;
                *(float4*)(dst + c) = o;
            }
        } else {
            const float* bias = (z == 0) ? bq : (z == 1) ? bk : bv;
            __nv_bfloat16 *dsth, *dstl;
            if (z == 0)      { dsth = g_qh;  dstl = g_ql;  }
            else if (z == 1) { dsth = g_knh; dstl = g_knl; }
            else             { dsth = g_vnh; dstl = g_vnl; }
            for (int hh = 0; hh < 2; hh++) {
                float v[64], o[64];
#pragma unroll
                for (int j = 0; j < 64; j++)
                    v[j] = Cr[hh * 64 + j] + bias[col0 + hh * 64 + j];
                if (z < 2) {
#pragma unroll
                    for (int d = 0; d < 32; d++) {
                        float cc = rcos[(t << 6) + d];
                        float ss = rsin[(t << 6) + d];
                        o[d]      = v[d] * cc - v[d + 32] * ss;
                        o[d + 32] = v[d + 32] * cc + v[d] * ss;
                    }
                    if (z == 0) {
#pragma unroll
                        for (int j = 0; j < 64; j++) o[j] *= QSC_;
                    }
                } else {
#pragma unroll
                    for (int j = 0; j < 64; j++) o[j] = v[j];
                }
                if (!valid) {
#pragma unroll
                    for (int j = 0; j < 64; j++) o[j] = 0.f;
                }
                int h = (col0 >> 6) + hh;
                size_t off = (((size_t)b * H_ + h) * T_ + t) * DH_;
#pragma unroll
                for (int j = 0; j < 64; j += 4) {
                    ushort4 hv, lv;
                    __nv_bfloat16 h0=__float2bfloat16_rn(o[j+0]), h1=__float2bfloat16_rn(o[j+1]);
                    __nv_bfloat16 h2=__float2bfloat16_rn(o[j+2]), h3=__float2bfloat16_rn(o[j+3]);
                    hv.x=__bfloat16_as_ushort(h0); hv.y=__bfloat16_as_ushort(h1);
                    hv.z=__bfloat16_as_ushort(h2); hv.w=__bfloat16_as_ushort(h3);
                    lv.x=__bfloat16_as_ushort(__float2bfloat16_rn(o[j+0]-__bfloat162float(h0)));
                    lv.y=__bfloat16_as_ushort(__float2bfloat16_rn(o[j+1]-__bfloat162float(h1)));
                    lv.z=__bfloat16_as_ushort(__float2bfloat16_rn(o[j+2]-__bfloat162float(h2)));
                    lv.w=__bfloat16_as_ushort(__float2bfloat16_rn(o[j+3]-__bfloat162float(h3)));
                    *(ushort4*)(dsth + off + j) = hv;
                    *(ushort4*)(dstl + off + j) = lv;
                }
            }
        }
    }
}

// ---------------- Flash attention on mma.sync ------------------------------------
// CTA: 128 q-rows x (b,h). 8 warps, 16 rows each. 64-key blocks, cp.async 2-stage.
// smem: Q hi/lo 2*18432 @0; stages: 36864 + s*36864, arrays kh,kl,vh,vl @ +9216 each
#define SMEM_ATTN_ 110592

__global__ void __launch_bounds__(256, 1) attn_mma_kernel(
    const int* __restrict__ plen, const int* __restrict__ nc)
{
    extern __shared__ __align__(128) char smem[];
    const uint32_t sbase = smem_u32(smem);

    int b = blockIdx.z, h = blockIdx.y, t0 = blockIdx.x * 128;
    int Nn = nc[b];
    if (t0 >= Nn) return;
    int Tp = plen[b]; Tp = Tp < 0 ? 0 : (Tp > P_ ? P_ : Tp);
    int Ltot   = Tp + Nn;
    int nPast  = (Tp + 63) >> 6;
    int newLen = Ltot - P_;
    int nNew   = newLen > 0 ? (newLen + 63) >> 6 : 0;
    int nblk   = nPast + nNew;
    int Tpad   = nPast << 6;
    int Z      = (P_ < Ltot ? P_ : Ltot) - Tpad; if (Z < 0) Z = 0;

    int tid = threadIdx.x, lane = tid & 31, wid = tid >> 5;
    size_t bh = (size_t)b * H_ + h;

    // ---- issue Q loads (group 0) ----
    {
        const __nv_bfloat16* qh = g_qh + (bh * T_ + t0) * DH_;
        const __nv_bfloat16* ql = g_ql + (bh * T_ + t0) * DH_;
#pragma unroll
        for (int u = 0; u < 8; u++) {
            int idx = tid + u * 256;
            int arr = idx >> 10;
            int rem = idx & 1023;
            int row = rem >> 3, c = rem & 7;
            const __nv_bfloat16* src = (arr ? ql : qh) + (size_t)row * DH_ + c * 8;
            cp_async16(sbase + arr * 18432 + row * 144 + c * 16, src);
        }
        asm volatile("cp.async.commit_group;" ::: "memory");
    }

    auto load_stage = [&](int i) {
        uint32_t SB = sbase + 36864 + (i & 1) * 36864;
        bool past = i < nPast;
        int j0 = past ? (i << 6) : (P_ + ((i - nPast) << 6));
        const __nv_bfloat16 *kh, *kl, *vh, *vl; size_t rb;
        if (past) { kh=g_pkh; kl=g_pkl; vh=g_pvh; vl=g_pvl; rb = bh * P_ + j0; }
        else      { kh=g_knh; kl=g_knl; vh=g_vnh; vl=g_vnl; rb = bh * T_ + (j0 - P_); }
#pragma unroll
        for (int u = 0; u < 8; u++) {
            int idx = tid + u * 256;
            int arr = idx >> 9;
            int rem = idx & 511;
            int row = rem >> 3, c = rem & 7;
            uint32_t dst = SB + arr * 9216 + row * 144 + c * 16;
            if (past && (j0 + row) >= Tp) {
                asm volatile("st.shared.v4.b32 [%0], {%1,%1,%1,%1};"
                             :: "r"(dst), "r"(0) : "memory");
            } else {
                const __nv_bfloat16* srcb = arr==0?kh:arr==1?kl:arr==2?vh:vl;
                cp_async16(dst, srcb + (rb + row) * DH_ + c * 8);
            }
        }
        asm volatile("cp.async.commit_group;" ::: "memory");
    };

    float m0 = -1e30f, m1 = -1e30f, l0 = 0.f, l1 = 0.f;
    float O[8][4];
#pragma unroll
    for (int nf = 0; nf < 8; nf++)
#pragma unroll
        for (int q = 0; q < 4; q++) O[nf][q] = 0.f;

    uint32_t Qh[4][4], Ql[4][4];

    if (nblk > 0) {
        load_stage(0);
        asm volatile("cp.async.wait_group 1;" ::: "memory");   // Q ready
        __syncthreads();
#pragma unroll
        for (int kk = 0; kk < 4; kk++) {
            uint32_t off = (uint32_t)((wid * 16 + (lane & 15)) * 144
                                      + (kk * 16 + ((lane >> 4) << 3)) * 2);
            ldm_x4(Qh[kk], sbase + off);
            ldm_x4(Ql[kk], sbase + 18432 + off);
        }
    } else {
        asm volatile("cp.async.wait_group 0;" ::: "memory");
    }

    for (int i = 0; i < nblk; i++) {
        __syncthreads();
        if (i + 1 < nblk) {
            load_stage(i + 1);
            asm volatile("cp.async.wait_group 1;" ::: "memory");
        } else {
            asm volatile("cp.async.wait_group 0;" ::: "memory");
        }
        __syncthreads();

        int j0 = (i < nPast) ? (i << 6) : (P_ + ((i - nPast) << 6));
        uint32_t SB = sbase + 36864 + (i & 1) * 36864;

        // ---- S = Q K^T (3-pass hi/lo) ----
        float S[8][4];
#pragma unroll
        for (int nf = 0; nf < 8; nf++)
#pragma unroll
            for (int q = 0; q < 4; q++) S[nf][q] = 0.f;
#pragma unroll
        for (int nf = 0; nf < 8; nf++) {
            uint32_t kfh[4][2], kfl[4][2];
#pragma unroll
            for (int kk = 0; kk < 4; kk++) {
                uint32_t off = (uint32_t)((nf * 8 + (lane & 7)) * 144
                                          + (kk * 16 + (((lane >> 3) & 1) << 3)) * 2);
                ldm_x2(kfh[kk], SB + off);
                ldm_x2(kfl[kk], SB + 9216 + off);
            }
#pragma unroll
            for (int kk = 0; kk < 4; kk++) {
                mma16816(S[nf], Qh[kk], kfh[kk]);
                mma16816(S[nf], Qh[kk], kfl[kk]);
                mma16816(S[nf], Ql[kk], kfh[kk]);
            }
        }

        // ---- mask keys >= Ltot ----
#pragma unroll
        for (int nf = 0; nf < 8; nf++) {
            int keyc = j0 + nf * 8 + ((lane & 3) << 1);
            if (keyc     >= Ltot) { S[nf][0] = -1e9f; S[nf][2] = -1e9f; }
            if (keyc + 1 >= Ltot) { S[nf][1] = -1e9f; S[nf][3] = -1e9f; }
        }

        // ---- online softmax (log2 units) ----
        float mx0 = -1e30f, mx1 = -1e30f;
#pragma unroll
        for (int nf = 0; nf < 8; nf++) {
            mx0 = fmaxf(mx0, fmaxf(S[nf][0], S[nf][1]));
            mx1 = fmaxf(mx1, fmaxf(S[nf][2], S[nf][3]));
        }
        mx0 = fmaxf(mx0, __shfl_xor_sync(0xffffffffu, mx0, 1));
        mx0 = fmaxf(mx0, __shfl_xor_sync(0xffffffffu, mx0, 2));
        mx1 = fmaxf(mx1, __shfl_xor_sync(0xffffffffu, mx1, 1));
        mx1 = fmaxf(mx1, __shfl_xor_sync(0xffffffffu, mx1, 2));
        float nm0 = fmaxf(m0, mx0), nm1 = fmaxf(m1, mx1);
        float a0 = ex2f(m0 - nm0), a1 = ex2f(m1 - nm1);
        m0 = nm0; m1 = nm1;
        float rs0 = 0.f, rs1 = 0.f;
#pragma unroll
        for (int nf = 0; nf < 8; nf++) {
            S[nf][0] = ex2f(S[nf][0] - nm0);
            S[nf][1] = ex2f(S[nf][1] - nm0);
            S[nf][2] = ex2f(S[nf][2] - nm1);
            S[nf][3] = ex2f(S[nf][3] - nm1);
            rs0 += S[nf][0] + S[nf][1];
            rs1 += S[nf][2] + S[nf][3];
        }
        rs0 += __shfl_xor_sync(0xffffffffu, rs0, 1);
        rs0 += __shfl_xor_sync(0xffffffffu, rs0, 2);
        rs1 += __shfl_xor_sync(0xffffffffu, rs1, 1);
        rs1 += __shfl_xor_sync(0xffffffffu, rs1, 2);
        l0 = l0 * a0 + rs0;
        l1 = l1 * a1 + rs1;
#pragma unroll
        for (int nf = 0; nf < 8; nf++) {
            O[nf][0] *= a0; O[nf][1] *= a0;
            O[nf][2] *= a1; O[nf][3] *= a1;
        }

        // ---- pack P into A-fragments (hi/lo) ----
        uint32_t Ph[4][4], Pl[4][4];
#pragma unroll
        for (int kk = 0; kk < 4; kk++) {
            float p0 = S[2*kk][0],   p1 = S[2*kk][1],   p2 = S[2*kk][2],   p3 = S[2*kk][3];
            float q0 = S[2*kk+1][0], q1 = S[2*kk+1][1], q2 = S[2*kk+1][2], q3 = S[2*kk+1][3];
            uint32_t u;
            u = packbf(p0, p1); Ph[kk][0] = u; Pl[kk][0] = packbf(p0 - bflo(u), p1 - bfhi(u));
            u = packbf(p2, p3); Ph[kk][1] = u; Pl[kk][1] = packbf(p2 - bflo(u), p3 - bfhi(u));
            u = packbf(q0, q1); Ph[kk][2] = u; Pl[kk][2] = packbf(q0 - bflo(u), q1 - bfhi(u));
            u = packbf(q2, q3); Ph[kk][3] = u; Pl[kk][3] = packbf(q2 - bflo(u), q3 - bfhi(u));
        }

        // ---- O += P V (3-pass hi/lo, V via ldmatrix.trans) ----
#pragma unroll
        for (int nf = 0; nf < 8; nf++) {
            uint32_t vfh[4][2], vfl[4][2];
#pragma unroll
            for (int kk = 0; kk < 4; kk++) {
                uint32_t off = (uint32_t)((kk * 16 + (lane & 15)) * 144 + nf * 16);
                ldm_x2t(vfh[kk], SB + 18432 + off);
                ldm_x2t(vfl[kk], SB + 27648 + off);
            }
#pragma unroll
            for (int kk = 0; kk < 4; kk++) {
                mma16816(O[nf], Ph[kk], vfh[kk]);
                mma16816(O[nf], Ph[kk], vfl[kk]);
                mma16816(O[nf], Pl[kk], vfh[kk]);
            }
        }
    }

    // ---- analytic zero-key term ----
    if (Z > 0) {
        float nm0 = fmaxf(m0, 0.f), nm1 = fmaxf(m1, 0.f);
        float a0 = ex2f(m0 - nm0), a1 = ex2f(m1 - nm1);
        l0 = l0 * a0 + (float)Z * ex2f(-nm0);
        l1 = l1 * a1 + (float)Z * ex2f(-nm1);
#pragma unroll
        for (int nf = 0; nf < 8; nf++) {
            O[nf][0] *= a0; O[nf][1] *= a0;
            O[nf][2] *= a1; O[nf][3] *= a1;
        }
    }

    // ---- normalize, stage to smem, write bf16 hi/lo attn ----
    float inv0 = 1.f / l0, inv1 = 1.f / l1;
    float* Os = (float*)smem;   // [128][68], fits in Q region (34816 <= 36864)
    __syncthreads();
    {
        int r0 = wid * 16 + (lane >> 2);
        int cb = (lane & 3) << 1;
#pragma unroll
        for (int nf = 0; nf < 8; nf++) {
            *(float2*)&Os[r0 * 68 + nf * 8 + cb] =
                make_float2(O[nf][0] * inv0, O[nf][1] * inv0);
            *(float2*)&Os[(r0 + 8) * 68 + nf * 8 + cb] =
                make_float2(O[nf][2] * inv1, O[nf][3] * inv1);
        }
    }
    __syncthreads();
    {
        int r = tid >> 1;
        int half = (tid & 1) * 32;
        int t = t0 + r;
        size_t orow = ((size_t)b * T_ + t) * DM_ + h * DH_ + half;
        const float* Or = Os + r * 68 + half;
#pragma unroll
        for (int j = 0; j < 32; j += 4) {
            float v0 = Or[j], v1 = Or[j+1], v2 = Or[j+2], v3 = Or[j+3];
            __nv_bfloat16 h0=__float2bfloat16_rn(v0), h1=__float2bfloat16_rn(v1);
            __nv_bfloat16 h2=__float2bfloat16_rn(v2), h3=__float2bfloat16_rn(v3);
            ushort4 hv, lv;
            hv.x=__bfloat16_as_ushort(h0); hv.y=__bfloat16_as_ushort(h1);
            hv.z=__bfloat16_as_ushort(h2); hv.w=__bfloat16_as_ushort(h3);
            lv.x=__bfloat16_as_ushort(__float2bfloat16_rn(v0-__bfloat162float(h0)));
            lv.y=__bfloat16_as_ushort(__float2bfloat16_rn(v1-__bfloat162float(h1)));
            lv.z=__bfloat16_as_ushort(__float2bfloat16_rn(v2-__bfloat162float(h2)));
            lv.w=__bfloat16_as_ushort(__float2bfloat16_rn(v3-__bfloat162float(h3)));
            *(ushort4*)(g_at_hi + orow + j) = hv;
            *(ushort4*)(g_at_lo + orow + j) = lv;
        }
    }
}

// ---------------- launch ----------------
extern "C" void kernel_launch(void* const* d_in, const int* in_sizes, int n_in,
                              void* d_out, int out_size)
{
    const float* x   = (const float*)d_in[0];
    const float* rc  = (const float*)d_in[1];
    const float* rs  = (const float*)d_in[2];
    const float* pk  = (const float*)d_in[3];
    const float* pv  = (const float*)d_in[4];
    const int*   pl  = (const int*)  d_in[5];
    const int*   nc  = (const int*)  d_in[7];
    const float* Wq  = (const float*)d_in[8];
    const float* bq  = (const float*)d_in[9];
    const float* Wk  = (const float*)d_in[10];
    const float* bk  = (const float*)d_in[11];
    const float* Wv  = (const float*)d_in[12];
    const float* bv  = (const float*)d_in[13];
    const float* Wo  = (const float*)d_in[14];
    const float* bo  = (const float*)d_in[15];
    float* out = (float*)d_out;

    cudaFuncSetAttribute(mma_gemm_kernel,
                         cudaFuncAttributeMaxDynamicSharedMemorySize, SMEM_GEMM_);
    cudaFuncSetAttribute(attn_mma_kernel,
                         cudaFuncAttributeMaxDynamicSharedMemorySize, SMEM_ATTN_);

    conv_split_kernel<<<(BT_*DM_)/(4*256), 256>>>(x);
    prep_w_kernel<<<dim3(32, 32, 4), 256>>>(Wq, Wk, Wv, Wo);
    prep_past_kernel<<<dim3((P_*DH_)/(4*256), B_*H_), 256>>>(pk, pv, pl);
    mma_gemm_kernel<<<dim3(8, 32, 3), 256, SMEM_GEMM_>>>(rc, rs, bq, bk, bv, bo, out, nc, 0);
    attn_mma_kernel<<<dim3(T_/128, H_, B_), 256, SMEM_ATTN_>>>(pl, nc);
    mma_gemm_kernel<<<dim3(8, 32, 1), 256, SMEM_GEMM_>>>(rc, rs, bq, bk, bv, bo, out, nc, 1);
}